// round 2
// baseline (speedup 1.0000x reference)
#include <cuda_runtime.h>
#include <cstdint>

#define NN        8192
#define KSEL      64
#define NTHREADS  256
#define CAP       1024

// Warp-aggregated shared-memory histogram add: one atomic per distinct bin
// per warp (data clusters in a few exponent bins; naive atomics serialize).
__device__ __forceinline__ void hist_add(uint32_t* hist, uint32_t bin, bool pred, int lane) {
    unsigned act = __ballot_sync(0xffffffffu, pred);
    if (pred) {
        unsigned same   = __match_any_sync(act, bin);
        int      leader = __ffs(same) - 1;
        if (lane == leader) atomicAdd(&hist[bin], (uint32_t)__popc(same));
    }
}

// Process one element in the output sweep: returns masked output value and
// ballot-compacts bucket-b candidates into the shared key buffer.
// Key = (valueBits << 16) | (0xFFFF ^ index): larger key == larger value,
// ties broken toward smaller index (top_k order). Warp-uniform call site.
__device__ __forceinline__ float proc_elem(uint32_t bits, uint32_t eidx, uint32_t b, bool deg,
                                           uint64_t* cand, uint32_t* cand_count, int lane) {
    bool keep, is_cand;
    if (deg) { keep = true; is_cand = false; }          // <K positives: all kept
    else {
        uint32_t byte = bits >> 24;
        keep    = byte > b;
        is_cand = (byte == b) && (bits != 0u);
    }
    unsigned act = __ballot_sync(0xffffffffu, is_cand);
    if (act) {
        int      leader = __ffs(act) - 1;
        uint32_t base   = 0;
        if (lane == leader) base = atomicAdd(cand_count, (uint32_t)__popc(act));
        base = __shfl_sync(0xffffffffu, base, leader);
        if (is_cand) {
            uint32_t pos = base + __popc(act & ((1u << lane) - 1u));
            if (pos < CAP)
                cand[pos] = ((uint64_t)bits << 16) | (uint64_t)(0xFFFFu ^ eidx);
        }
    }
    return keep ? __uint_as_float(bits) : 0.0f;
}

extern __shared__ uint32_t sdata[];   // NN uint32 (relu'd float bits)

__global__ __launch_bounds__(NTHREADS)
void topk_mask_kernel(const float* __restrict__ A, float* __restrict__ out)
{
    __shared__ uint32_t hist[256];
    __shared__ uint32_t wsum[8];
    __shared__ uint64_t cand[CAP];
    __shared__ uint32_t cand_count;
    __shared__ uint32_t sh_b, sh_kp, sh_deg;

    const int    tid  = threadIdx.x;
    const int    lane = tid & 31;
    const size_t row  = blockIdx.x;

    const float4* arow = reinterpret_cast<const float4*>(A + row * (size_t)NN);
    float4*       orow = reinterpret_cast<float4*>(out + row * (size_t)NN);
    uint4*        s4   = reinterpret_cast<uint4*>(sdata);

    hist[tid] = 0;
    if (tid == 0) { cand_count = 0; sh_b = 0; sh_kp = 0; sh_deg = 0; }
    __syncthreads();

    // ---- Sweep 1: load + relu + STS + top-byte histogram (skip zeros) ----
    #pragma unroll
    for (int i = tid; i < NN / 4; i += NTHREADS) {
        float4 v = arow[i];
        uint32_t b0 = (v.x > 0.0f) ? __float_as_uint(v.x) : 0u;
        uint32_t b1 = (v.y > 0.0f) ? __float_as_uint(v.y) : 0u;
        uint32_t b2 = (v.z > 0.0f) ? __float_as_uint(v.z) : 0u;
        uint32_t b3 = (v.w > 0.0f) ? __float_as_uint(v.w) : 0u;
        s4[i] = make_uint4(b0, b1, b2, b3);
        hist_add(hist, b0 >> 24, b0 != 0u, lane);
        hist_add(hist, b1 >> 24, b1 != 0u, lane);
        hist_add(hist, b2 >> 24, b2 != 0u, lane);
        hist_add(hist, b3 >> 24, b3 != 0u, lane);
    }
    __syncthreads();

    // ---- Suffix scan over 256 bins: find crossing bucket b and in-bucket rank kp ----
    {
        const uint32_t v0 = hist[tid];
        uint32_t v = v0;
        #pragma unroll
        for (int d = 1; d < 32; d <<= 1) {
            uint32_t o = __shfl_down_sync(0xffffffffu, v, d);
            if (lane + d < 32) v += o;
        }
        if (lane == 0) wsum[tid >> 5] = v;
        __syncthreads();
        uint32_t hi = 0;
        #pragma unroll
        for (int w = 0; w < 8; ++w) if (w > (tid >> 5)) hi += wsum[w];
        const uint32_t s   = v + hi;        // count of elements with top byte >= tid
        const uint32_t nxt = s - v0;        // count with top byte  > tid
        if (tid == 0 && s < KSEL) sh_deg = 1;
        if (s >= KSEL && nxt < KSEL) { sh_b = (uint32_t)tid; sh_kp = KSEL - nxt; }
        __syncthreads();
    }

    const uint32_t b   = sh_b;
    const uint32_t kp  = sh_kp;
    const bool     deg = (sh_deg != 0);

    // ---- Sweep 2 (fused): masked coalesced output + candidate compaction ----
    #pragma unroll
    for (int i = tid; i < NN / 4; i += NTHREADS) {
        uint4 bb = s4[i];
        float4 o;
        o.x = proc_elem(bb.x, 4u * i + 0u, b, deg, cand, &cand_count, lane);
        o.y = proc_elem(bb.y, 4u * i + 1u, b, deg, cand, &cand_count, lane);
        o.z = proc_elem(bb.z, 4u * i + 2u, b, deg, cand, &cand_count, lane);
        o.w = proc_elem(bb.w, 4u * i + 3u, b, deg, cand, &cand_count, lane);
        orow[i] = o;
    }
    __syncthreads();

    // ---- Exact ranking of bucket-b candidates; scatter the kp winners ----
    if (!deg) {
        const uint32_t C = cand_count;
        if (C <= CAP) {
            for (uint32_t j = tid; j < C; j += NTHREADS) {
                const uint64_t kj = cand[j];
                uint32_t r = 0;
                for (uint32_t m = 0; m < C; ++m)
                    r += (cand[m] > kj) ? 1u : 0u;
                if (r < kp) {
                    const uint32_t idx = 0xFFFFu ^ (uint32_t)(kj & 0xFFFFu);
                    out[row * (size_t)NN + idx] = __uint_as_float((uint32_t)(kj >> 16));
                }
            }
        } else {
            // Robustness fallback (pathological duplicate-heavy input; never
            // taken for continuous random data). Exact full-scan ranking.
            for (int i = tid; i < NN; i += NTHREADS) {
                const uint32_t v = sdata[i];
                if (v != 0u && (v >> 24) == b) {
                    uint32_t r = 0;
                    for (int j = 0; j < NN; ++j) {
                        const uint32_t w = sdata[j];
                        if (w != 0u && (w >> 24) == b)
                            r += (w > v || (w == v && j < i)) ? 1u : 0u;
                    }
                    if (r < kp) out[row * (size_t)NN + i] = __uint_as_float(v);
                }
            }
        }
    }
}

extern "C" void kernel_launch(void* const* d_in, const int* in_sizes, int n_in,
                              void* d_out, int out_size) {
    const float* A   = (const float*)d_in[0];
    float*       out = (float*)d_out;
    (void)in_sizes; (void)n_in; (void)out_size;   // idx (d_in[1]) unused by the reference
    topk_mask_kernel<<<NN, NTHREADS, NN * sizeof(uint32_t)>>>(A, out);
}

// round 3
// speedup vs baseline: 1.7797x; 1.7797x over previous
#include <cuda_runtime.h>
#include <cstdint>

#define NN        8192
#define KSEL      64
#define NTHREADS  256
#define CAP       768
#define THRESH    2.0f

__device__ __forceinline__ uint64_t make_key(uint32_t bits, uint32_t idx) {
    // larger key == larger value; ties -> smaller index (top_k order)
    return ((uint64_t)bits << 16) | (uint64_t)(0xFFFFu ^ idx);
}

// Warp-aggregated histogram add (fallback path only).
__device__ __forceinline__ void hist_add(uint32_t* hist, uint32_t bin, bool pred, int lane) {
    unsigned act = __ballot_sync(0xffffffffu, pred);
    if (pred) {
        unsigned same   = __match_any_sync(act, bin);
        int      leader = __ffs(same) - 1;
        if (lane == leader) atomicAdd(&hist[bin], (uint32_t)__popc(same));
    }
}

__global__ __launch_bounds__(NTHREADS)
void topk_mask_kernel(const float* __restrict__ A, float* __restrict__ out)
{
    __shared__ uint64_t cand[CAP];
    __shared__ uint32_t cand_count;
    __shared__ uint32_t hist[256];
    __shared__ uint32_t wsum[8];
    __shared__ uint32_t sh_b, sh_kp, sh_deg;

    const int    tid  = threadIdx.x;
    const int    lane = tid & 31;
    const size_t row  = blockIdx.x;

    const float*  arowf = A + row * (size_t)NN;
    const float4* arow  = reinterpret_cast<const float4*>(arowf);
    float4*       orow  = reinterpret_cast<float4*>(out + row * (size_t)NN);

    if (tid == 0) cand_count = 0;
    __syncthreads();

    const float4 z4 = make_float4(0.0f, 0.0f, 0.0f, 0.0f);

    // ---- Single sweep: read A, zero-fill out, compact candidates (v >= THRESH) ----
    #pragma unroll
    for (int i = tid; i < NN / 4; i += NTHREADS) {
        float4 v = arow[i];
        orow[i] = z4;                       // independent of everything: pure BW
        uint32_t m = 0;
        m |= (v.x >= THRESH) ? 1u : 0u;
        m |= (v.y >= THRESH) ? 2u : 0u;
        m |= (v.z >= THRESH) ? 4u : 0u;
        m |= (v.w >= THRESH) ? 8u : 0u;
        const int cnt = __popc(m);
        const unsigned act = __ballot_sync(0xffffffffu, cnt != 0);
        if (act) {
            // warp inclusive scan of per-thread candidate counts
            uint32_t p = (uint32_t)cnt;
            #pragma unroll
            for (int d = 1; d < 32; d <<= 1) {
                uint32_t t = __shfl_up_sync(0xffffffffu, p, d);
                if (lane >= d) p += t;
            }
            const uint32_t total = __shfl_sync(0xffffffffu, p, 31);
            uint32_t base = 0;
            if (lane == 31) base = atomicAdd(&cand_count, total);
            base = __shfl_sync(0xffffffffu, base, 31);
            uint32_t off = base + p - (uint32_t)cnt;
            if (m & 1u) { if (off < CAP) cand[off] = make_key(__float_as_uint(v.x), 4u * i + 0u); off++; }
            if (m & 2u) { if (off < CAP) cand[off] = make_key(__float_as_uint(v.y), 4u * i + 1u); off++; }
            if (m & 4u) { if (off < CAP) cand[off] = make_key(__float_as_uint(v.z), 4u * i + 2u); off++; }
            if (m & 8u) { if (off < CAP) cand[off] = make_key(__float_as_uint(v.w), 4u * i + 3u); off++; }
        }
    }
    __syncthreads();

    const uint32_t C = cand_count;
    if (C >= KSEL && C <= CAP) {
        // Fast path valid: the 64th-largest is >= THRESH, so cand holds the whole
        // top-64. Exact rank (value desc, index asc) and scatter winners.
        for (uint32_t j = tid; j < C; j += NTHREADS) {
            const uint64_t kj = cand[j];
            uint32_t r = 0;
            for (uint32_t mm = 0; mm < C; ++mm)
                r += (cand[mm] > kj) ? 1u : 0u;         // cand[mm] is a broadcast LDS
            if (r < KSEL) {
                const uint32_t idx = 0xFFFFu ^ (uint32_t)(kj & 0xFFFFu);
                out[row * (size_t)NN + idx] = __uint_as_float((uint32_t)(kj >> 16));
            }
        }
        return;
    }

    // ================= Exact fallback (bracket failed; never taken on N(0,1)) ==========
    hist[tid] = 0;
    if (tid == 0) { sh_b = 0; sh_kp = 0; sh_deg = 0; cand_count = 0; }
    __syncthreads();

    for (int i = tid; i < NN / 4; i += NTHREADS) {
        float4 v = arow[i];
        uint32_t b0 = (v.x > 0.0f) ? __float_as_uint(v.x) : 0u;
        uint32_t b1 = (v.y > 0.0f) ? __float_as_uint(v.y) : 0u;
        uint32_t b2 = (v.z > 0.0f) ? __float_as_uint(v.z) : 0u;
        uint32_t b3 = (v.w > 0.0f) ? __float_as_uint(v.w) : 0u;
        hist_add(hist, b0 >> 24, b0 != 0u, lane);
        hist_add(hist, b1 >> 24, b1 != 0u, lane);
        hist_add(hist, b2 >> 24, b2 != 0u, lane);
        hist_add(hist, b3 >> 24, b3 != 0u, lane);
    }
    __syncthreads();

    {   // suffix scan over 256 byte bins
        const uint32_t v0 = hist[tid];
        uint32_t v = v0;
        #pragma unroll
        for (int d = 1; d < 32; d <<= 1) {
            uint32_t o = __shfl_down_sync(0xffffffffu, v, d);
            if (lane + d < 32) v += o;
        }
        if (lane == 0) wsum[tid >> 5] = v;
        __syncthreads();
        uint32_t hi = 0;
        #pragma unroll
        for (int w = 0; w < 8; ++w) if (w > (tid >> 5)) hi += wsum[w];
        const uint32_t s   = v + hi;     // count with top byte >= tid
        const uint32_t nxt = s - v0;     // count with top byte  > tid
        if (tid == 0 && s < KSEL) sh_deg = 1;
        if (s >= KSEL && nxt < KSEL) { sh_b = (uint32_t)tid; sh_kp = KSEL - nxt; }
        __syncthreads();
    }
    const uint32_t b   = sh_b;
    const uint32_t kp  = sh_kp;
    const bool     deg = (sh_deg != 0);

    // zeros are already in place from the first sweep; write survivors only
    for (int i = tid; i < NN; i += NTHREADS) {
        const float    v    = arowf[i];
        const uint32_t bits = (v > 0.0f) ? __float_as_uint(v) : 0u;
        if (deg) {
            if (bits) out[row * (size_t)NN + i] = v;   // <K positives: keep all
        } else if (bits) {
            const uint32_t byte = bits >> 24;
            if (byte > b) out[row * (size_t)NN + i] = v;
            else if (byte == b) {
                const uint32_t p = atomicAdd(&cand_count, 1u);
                if (p < CAP) cand[p] = make_key(bits, (uint32_t)i);
            }
        }
    }
    __syncthreads();

    if (!deg) {
        const uint32_t C2 = cand_count;
        if (C2 <= CAP) {
            for (uint32_t j = tid; j < C2; j += NTHREADS) {
                const uint64_t kj = cand[j];
                uint32_t r = 0;
                for (uint32_t mm = 0; mm < C2; ++mm)
                    r += (cand[mm] > kj) ? 1u : 0u;
                if (r < kp) {
                    const uint32_t idx = 0xFFFFu ^ (uint32_t)(kj & 0xFFFFu);
                    out[row * (size_t)NN + idx] = __uint_as_float((uint32_t)(kj >> 16));
                }
            }
        } else {
            // ultra-rare duplicate-heavy rows: O(N) exact rank per candidate
            for (int i = tid; i < NN; i += NTHREADS) {
                const float    v    = arowf[i];
                const uint32_t bits = (v > 0.0f) ? __float_as_uint(v) : 0u;
                if (bits && (bits >> 24) == b) {
                    const uint64_t kj = make_key(bits, (uint32_t)i);
                    uint32_t r = 0;
                    for (int j2 = 0; j2 < NN; ++j2) {
                        const float    w  = arowf[j2];
                        const uint32_t wb = (w > 0.0f) ? __float_as_uint(w) : 0u;
                        if (wb && (wb >> 24) == b && make_key(wb, (uint32_t)j2) > kj) ++r;
                    }
                    if (r < kp) out[row * (size_t)NN + i] = v;
                }
            }
        }
    }
}

extern "C" void kernel_launch(void* const* d_in, const int* in_sizes, int n_in,
                              void* d_out, int out_size) {
    const float* A   = (const float*)d_in[0];
    float*       out = (float*)d_out;
    (void)in_sizes; (void)n_in; (void)out_size;   // idx (d_in[1]) unused by the reference
    topk_mask_kernel<<<NN, NTHREADS>>>(A, out);
}

// round 4
// speedup vs baseline: 1.9815x; 1.1134x over previous
#include <cuda_runtime.h>
#include <cstdint>

#define NN        8192
#define KSEL      64
#define NTHREADS  256
#define CAP       768
#define THRESH    2.0f

__device__ __forceinline__ uint64_t make_key(uint32_t bits, uint32_t idx) {
    // larger key == larger value; ties -> smaller index (top_k order)
    return ((uint64_t)bits << 16) | (uint64_t)(0xFFFFu ^ idx);
}

// Warp-aggregated histogram add (fallback path only).
__device__ __forceinline__ void hist_add(uint32_t* hist, uint32_t bin, bool pred, int lane) {
    unsigned act = __ballot_sync(0xffffffffu, pred);
    if (pred) {
        unsigned same   = __match_any_sync(act, bin);
        int      leader = __ffs(same) - 1;
        if (lane == leader) atomicAdd(&hist[bin], (uint32_t)__popc(same));
    }
}

__global__ __launch_bounds__(NTHREADS)
void topk_mask_kernel(const float* __restrict__ A, float* __restrict__ out)
{
    __shared__ uint64_t cand[CAP];
    __shared__ uint32_t cand_count;
    __shared__ uint32_t hist[256];
    __shared__ uint32_t wsum[8];
    __shared__ uint32_t sh_b, sh_kp, sh_deg;

    const int    tid  = threadIdx.x;
    const int    lane = tid & 31;
    const size_t row  = blockIdx.x;

    const float*  arowf = A + row * (size_t)NN;
    const float4* arow  = reinterpret_cast<const float4*>(arowf);
    float4*       orow  = reinterpret_cast<float4*>(out + row * (size_t)NN);

    if (tid == 0) cand_count = 0;
    __syncthreads();

    const float4 z4 = make_float4(0.0f, 0.0f, 0.0f, 0.0f);

    // ---- Single sweep: read A, zero-fill out, push candidates (v >= THRESH) ----
    // Hot path per float4: LDG.128 + STG.128 + 3 FMNMX + 1 FSETP + branch.
    // Candidate path runs with ~1-3 active lanes/warp; order in cand[] is
    // irrelevant (rank phase orders by key), so no ballot/scan machinery.
    #pragma unroll
    for (int i = tid; i < NN / 4; i += NTHREADS) {
        float4 v = arow[i];
        orow[i] = z4;                               // independent: pure BW
        const float vmax = fmaxf(fmaxf(v.x, v.y), fmaxf(v.z, v.w));
        if (vmax >= THRESH) {
            uint32_t m = 0;
            m |= (v.x >= THRESH) ? 1u : 0u;
            m |= (v.y >= THRESH) ? 2u : 0u;
            m |= (v.z >= THRESH) ? 4u : 0u;
            m |= (v.w >= THRESH) ? 8u : 0u;
            uint32_t off = atomicAdd(&cand_count, (uint32_t)__popc(m));
            if (m & 1u) { if (off < CAP) cand[off] = make_key(__float_as_uint(v.x), 4u * i + 0u); off++; }
            if (m & 2u) { if (off < CAP) cand[off] = make_key(__float_as_uint(v.y), 4u * i + 1u); off++; }
            if (m & 4u) { if (off < CAP) cand[off] = make_key(__float_as_uint(v.z), 4u * i + 2u); off++; }
            if (m & 8u) { if (off < CAP) cand[off] = make_key(__float_as_uint(v.w), 4u * i + 3u); off++; }
        }
    }
    __syncthreads();

    const uint32_t C = cand_count;
    if (C >= KSEL && C <= CAP) {
        // Fast path valid: the 64th-largest is >= THRESH, so cand holds the whole
        // top-64. Exact rank (value desc, index asc) and scatter winners.
        for (uint32_t j = tid; j < C; j += NTHREADS) {
            const uint64_t kj = cand[j];
            uint32_t r = 0;
            for (uint32_t mm = 0; mm < C; ++mm)
                r += (cand[mm] > kj) ? 1u : 0u;        // broadcast LDS
            if (r < KSEL) {
                const uint32_t idx = 0xFFFFu ^ (uint32_t)(kj & 0xFFFFu);
                out[row * (size_t)NN + idx] = __uint_as_float((uint32_t)(kj >> 16));
            }
        }
        return;
    }

    // ================= Exact fallback (bracket failed; never taken on N(0,1)) =========
    hist[tid] = 0;
    if (tid == 0) { sh_b = 0; sh_kp = 0; sh_deg = 0; cand_count = 0; }
    __syncthreads();

    for (int i = tid; i < NN / 4; i += NTHREADS) {
        float4 v = arow[i];
        uint32_t b0 = (v.x > 0.0f) ? __float_as_uint(v.x) : 0u;
        uint32_t b1 = (v.y > 0.0f) ? __float_as_uint(v.y) : 0u;
        uint32_t b2 = (v.z > 0.0f) ? __float_as_uint(v.z) : 0u;
        uint32_t b3 = (v.w > 0.0f) ? __float_as_uint(v.w) : 0u;
        hist_add(hist, b0 >> 24, b0 != 0u, lane);
        hist_add(hist, b1 >> 24, b1 != 0u, lane);
        hist_add(hist, b2 >> 24, b2 != 0u, lane);
        hist_add(hist, b3 >> 24, b3 != 0u, lane);
    }
    __syncthreads();

    {   // suffix scan over 256 byte bins
        const uint32_t v0 = hist[tid];
        uint32_t v = v0;
        #pragma unroll
        for (int d = 1; d < 32; d <<= 1) {
            uint32_t o = __shfl_down_sync(0xffffffffu, v, d);
            if (lane + d < 32) v += o;
        }
        if (lane == 0) wsum[tid >> 5] = v;
        __syncthreads();
        uint32_t hi = 0;
        #pragma unroll
        for (int w = 0; w < 8; ++w) if (w > (tid >> 5)) hi += wsum[w];
        const uint32_t s   = v + hi;     // count with top byte >= tid
        const uint32_t nxt = s - v0;     // count with top byte  > tid
        if (tid == 0 && s < KSEL) sh_deg = 1;
        if (s >= KSEL && nxt < KSEL) { sh_b = (uint32_t)tid; sh_kp = KSEL - nxt; }
        __syncthreads();
    }
    const uint32_t b   = sh_b;
    const uint32_t kp  = sh_kp;
    const bool     deg = (sh_deg != 0);

    // zeros are already in place from the first sweep; write survivors only
    for (int i = tid; i < NN; i += NTHREADS) {
        const float    v    = arowf[i];
        const uint32_t bits = (v > 0.0f) ? __float_as_uint(v) : 0u;
        if (deg) {
            if (bits) out[row * (size_t)NN + i] = v;   // <K positives: keep all
        } else if (bits) {
            const uint32_t byte = bits >> 24;
            if (byte > b) out[row * (size_t)NN + i] = v;
            else if (byte == b) {
                const uint32_t p = atomicAdd(&cand_count, 1u);
                if (p < CAP) cand[p] = make_key(bits, (uint32_t)i);
            }
        }
    }
    __syncthreads();

    if (!deg) {
        const uint32_t C2 = cand_count;
        if (C2 <= CAP) {
            for (uint32_t j = tid; j < C2; j += NTHREADS) {
                const uint64_t kj = cand[j];
                uint32_t r = 0;
                for (uint32_t mm = 0; mm < C2; ++mm)
                    r += (cand[mm] > kj) ? 1u : 0u;
                if (r < kp) {
                    const uint32_t idx = 0xFFFFu ^ (uint32_t)(kj & 0xFFFFu);
                    out[row * (size_t)NN + idx] = __uint_as_float((uint32_t)(kj >> 16));
                }
            }
        } else {
            // ultra-rare duplicate-heavy rows: O(N) exact rank per candidate
            for (int i = tid; i < NN; i += NTHREADS) {
                const float    v    = arowf[i];
                const uint32_t bits = (v > 0.0f) ? __float_as_uint(v) : 0u;
                if (bits && (bits >> 24) == b) {
                    const uint64_t kj = make_key(bits, (uint32_t)i);
                    uint32_t r = 0;
                    for (int j2 = 0; j2 < NN; ++j2) {
                        const float    w  = arowf[j2];
                        const uint32_t wb = (w > 0.0f) ? __float_as_uint(w) : 0u;
                        if (wb && (wb >> 24) == b && make_key(wb, (uint32_t)j2) > kj) ++r;
                    }
                    if (r < kp) out[row * (size_t)NN + i] = v;
                }
            }
        }
    }
}

extern "C" void kernel_launch(void* const* d_in, const int* in_sizes, int n_in,
                              void* d_out, int out_size) {
    const float* A   = (const float*)d_in[0];
    float*       out = (float*)d_out;
    (void)in_sizes; (void)n_in; (void)out_size;   // idx (d_in[1]) unused by the reference
    topk_mask_kernel<<<NN, NTHREADS>>>(A, out);
}